// round 10
// baseline (speedup 1.0000x reference)
#include <cuda_runtime.h>
#include <cuda_bf16.h>
#include <mma.h>
#include <math.h>
#include <stdint.h>

using namespace nvcuda;

// Problem constants
#define BQ 2048
#define KQ 49
#define DQ 2048

// Scratch
__device__ float g_wgt[(size_t)BQ * KQ];   // W_gt[b][k]
__device__ float g_sent[BQ];               // sent logit per batch

// ---------------------------------------------------------------------------
// Kernel A: 512 threads, warp-per-row, 16 batch rows per CTA (128 CTAs)
// ---------------------------------------------------------------------------
#define A_BM 16
#define A_DC 64
#define A_STR 68

__global__ void __launch_bounds__(512) k_wgt_sent(
    const float* __restrict__ h_t, const float* __restrict__ s_t,
    const float* __restrict__ W_g, const float* __restrict__ W_s,
    const float* __restrict__ w_h_s)
{
    __shared__ float sh[A_BM * A_STR];
    __shared__ float ss[A_BM * A_STR];
    __shared__ float sg[64 * A_STR];
    __shared__ float sw[64 * A_STR];

    const int tid = threadIdx.x;
    const int tx = tid & 31;   // k-lane: k = tx, tx+32
    const int ty = tid >> 5;   // batch row 0..15 (one warp per row)
    const int b0 = blockIdx.x * A_BM;

    float accG[2] = {0.f, 0.f};
    float accS[2] = {0.f, 0.f};

    for (int c = 0; c < DQ; c += A_DC) {
        if (tid < 512) {
            // h/s tiles: 16 rows x 16 float4 = 256 each; threads 0-255 h, 256-511 s
            if (tid < 256) {
                int r = tid >> 4, u = tid & 15;
                *(float4*)(sh + r * A_STR + 4 * u) =
                    *(const float4*)(h_t + (size_t)(b0 + r) * DQ + c + 4 * u);
            } else {
                int t2 = tid - 256;
                int r = t2 >> 4, u = t2 & 15;
                *(float4*)(ss + r * A_STR + 4 * u) =
                    *(const float4*)(s_t + (size_t)(b0 + r) * DQ + c + 4 * u);
            }
        }
        for (int t = tid; t < KQ * 16; t += 512) {
            int k = t >> 4, u = t & 15;
            *(float4*)(sg + k * A_STR + 4 * u) =
                *(const float4*)(W_g + (size_t)k * DQ + c + 4 * u);
            *(float4*)(sw + k * A_STR + 4 * u) =
                *(const float4*)(W_s + (size_t)k * DQ + c + 4 * u);
        }
        __syncthreads();

        #pragma unroll 8
        for (int p = 0; p < A_DC / 2; ++p) {
            float2 ah = *(const float2*)(sh + ty * A_STR + 2 * p);
            float2 as = *(const float2*)(ss + ty * A_STR + 2 * p);
            #pragma unroll
            for (int j = 0; j < 2; ++j) {
                int k = tx + 32 * j;
                float2 bg = *(const float2*)(sg + k * A_STR + 2 * p);
                float2 bs = *(const float2*)(sw + k * A_STR + 2 * p);
                accG[j] = fmaf(ah.x, bg.x, fmaf(ah.y, bg.y, accG[j]));
                accS[j] = fmaf(as.x, bs.x, fmaf(as.y, bs.y, accS[j]));
            }
        }
        __syncthreads();
    }

    float part = 0.f;
    #pragma unroll
    for (int j = 0; j < 2; ++j) {
        int k = tx + 32 * j;
        if (k < KQ) {
            g_wgt[(size_t)(b0 + ty) * KQ + k] = accG[j];
            part += tanhf(accS[j] + accG[j]) * w_h_s[k];
        }
    }
    #pragma unroll
    for (int off = 16; off; off >>= 1)
        part += __shfl_xor_sync(0xffffffffu, part, off);
    if (tx == 0) g_sent[b0 + ty] = part;
}

// ---------------------------------------------------------------------------
// Main kernel: 2 batches per CTA, 512 threads (16 warps), WMMA tf32 GEMM
// M=128 N=64 K=2048, 4-stage cp.async ring, occ 2 (32 warps/SM).
// ---------------------------------------------------------------------------
#define BPC 2
#define KC 32
#define NCHUNK (DQ / KC)         // 64
#define T_STR 36
#define C_STR 68

// stage: A 128x36 (4608 f) then B 64x36 (2304 f)
#define STG_F 6912
#define STG_BYTES (STG_F * 4)    // 27648
#define F_B    4608
#define F_WGT  (4 * STG_F)       // 27648: wgt[2][64]
#define F_WH   (F_WGT + 128)
#define F_LOG  (F_WGT + 192)
#define F_PROB (F_WGT + 320)
#define SMEM_BYTES 112640        // 110 KB -> occupancy 2

__device__ __forceinline__ uint32_t smem_u32(const void* p) {
    return (uint32_t)__cvta_generic_to_shared(p);
}
__device__ __forceinline__ void cp16(uint32_t dst, const void* src) {
    asm volatile("cp.async.cg.shared.global [%0], [%1], 16;" :: "r"(dst), "l"(src));
}

__global__ void __launch_bounds__(512) k_main(
    const float* __restrict__ V, const float* __restrict__ h_t,
    const float* __restrict__ s_t, const float* __restrict__ W_v,
    const float* __restrict__ w_h, float* __restrict__ out)
{
    extern __shared__ float sm[];
    const int tid = threadIdx.x;
    const int wid = tid >> 5;
    const int b = blockIdx.x;          // batches 2b, 2b+1

    if (tid < 64)  sm[F_WH + tid] = (tid < KQ) ? w_h[tid] : 0.f;
    else if (tid >= 64 && tid < 192) {
        int t2 = tid - 64;
        int bt = t2 >> 6, k = t2 & 63;
        sm[F_WGT + t2] = (k < KQ) ? g_wgt[(size_t)(2 * b + bt) * KQ + k] : 0.f;
    }

    // ---- per-thread cp.async address table (once); <=3 entries ----
    const float* srcs[3];
    uint32_t dsts[3];
    int nCp = 0;
    for (int t = tid; t < 1536; t += 512) {
        if (t < 1024) {                       // A: rows 0..127 (bt*64+vr, vr<49)
            int row = t >> 3, u = t & 7;
            int bt = row >> 6, vr = row & 63;
            if (vr >= KQ) continue;
            srcs[nCp] = V + ((size_t)(2 * b + bt) * KQ + vr) * DQ + 4 * u;
            dsts[nCp] = smem_u32(sm + row * T_STR + 4 * u);
            nCp++;
        } else {                              // B: rows 0..63 (<49)
            int tt = t - 1024;
            int row = tt >> 3, u = tt & 7;
            if (row >= KQ) continue;
            srcs[nCp] = W_v + (size_t)row * DQ + 4 * u;
            dsts[nCp] = smem_u32(sm + F_B + row * T_STR + 4 * u);
            nCp++;
        }
    }

    auto issue_chunk = [&](int cc) {
        const uint32_t stg = (uint32_t)(cc & 3) * STG_BYTES;
        const int off = cc * KC;
        #pragma unroll
        for (int j = 0; j < 3; ++j)
            if (j < nCp) cp16(dsts[j] + stg, srcs[j] + off);
    };

    // warp tile: 16 rows x 32 cols. mi = wid>>1 (0..7), nh = wid&1
    const int mi = wid >> 1;
    const int nh = wid & 1;

    wmma::fragment<wmma::accumulator, 16, 16, 8, float> acc[2];
    wmma::fill_fragment(acc[0], 0.f);
    wmma::fill_fragment(acc[1], 0.f);

    issue_chunk(0); asm volatile("cp.async.commit_group;" ::: "memory");
    issue_chunk(1); asm volatile("cp.async.commit_group;" ::: "memory");
    issue_chunk(2); asm volatile("cp.async.commit_group;" ::: "memory");

    for (int c = 0; c < NCHUNK; ++c) {
        asm volatile("cp.async.wait_group 2;" ::: "memory");
        __syncthreads();
        if (c + 3 < NCHUNK) issue_chunk(c + 3);
        asm volatile("cp.async.commit_group;" ::: "memory");

        const float* St = sm + (c & 3) * STG_F;
        #pragma unroll
        for (int s = 0; s < 4; ++s) {
            wmma::fragment<wmma::matrix_a, 16, 16, 8, wmma::precision::tf32,
                           wmma::row_major> af;
            wmma::load_matrix_sync(af, St + (mi * 16) * T_STR + s * 8, T_STR);
            wmma::fragment<wmma::matrix_b, 16, 16, 8, wmma::precision::tf32,
                           wmma::col_major> bf[2];
            wmma::load_matrix_sync(bf[0], St + F_B + (nh * 32 +  0) * T_STR + s * 8, T_STR);
            wmma::load_matrix_sync(bf[1], St + F_B + (nh * 32 + 16) * T_STR + s * 8, T_STR);
            // no __float_to_tf32: HMMA.TF32 truncates fp32 inputs in HW
            wmma::mma_sync(acc[0], af, bf[0], acc[0]);
            wmma::mma_sync(acc[1], af, bf[1], acc[1]);
        }
    }
    __syncthreads();   // all compute done before C scratch overwrites stages

    // ---- store C (128x68) ----
    float* Cs = sm;
    wmma::store_matrix_sync(Cs + (mi * 16) * C_STR + nh * 32,      acc[0], C_STR,
                            wmma::mem_row_major);
    wmma::store_matrix_sync(Cs + (mi * 16) * C_STR + nh * 32 + 16, acc[1], C_STR,
                            wmma::mem_row_major);
    __syncthreads();

    // ---- logits: 14 FULL warps (448 threads); 4 threads per row ----
    if (tid < 448) {
        const int t  = tid >> 2;          // 0..111
        const int kg = tid & 3;
        const int bt = (t >= 56);
        const int l  = t - 56 * bt;       // 0..55
        float z = 0.f;
        if (l < KQ) {
            const int crow = bt * 64 + l;
            #pragma unroll
            for (int j = 0; j < 13; ++j) {
                int k = kg + 4 * j;
                if (k < KQ)
                    z += tanhf(Cs[crow * C_STR + k] + sm[F_WGT + 64 * bt + k])
                         * sm[F_WH + k];
            }
        }
        z += __shfl_xor_sync(0xffffffffu, z, 1);
        z += __shfl_xor_sync(0xffffffffu, z, 2);
        if (kg == 0 && l < KQ) sm[F_LOG + 64 * bt + l] = z;
    }
    if (tid < 2) sm[F_LOG + 64 * tid + KQ] = g_sent[2 * b + tid];
    __syncthreads();

    // ---- two softmaxes: warps 0/1 ----
    if (tid < 64) {
        const int w  = tid >> 5;
        const int tx = tid & 31;
        const float* sLog = sm + F_LOG + 64 * w;
        float* sProb = sm + F_PROB + 64 * w;
        float v0 = (tx < 50) ? sLog[tx] : -3.402823466e38f;
        float v1 = (tx < 18) ? sLog[tx + 32] : -3.402823466e38f;
        float m = fmaxf(v0, v1);
        #pragma unroll
        for (int off = 16; off; off >>= 1)
            m = fmaxf(m, __shfl_xor_sync(0xffffffffu, m, off));
        float e0 = (tx < 50) ? expf(v0 - m) : 0.f;
        float e1 = (tx < 18) ? expf(v1 - m) : 0.f;
        float ssum = e0 + e1;
        #pragma unroll
        for (int off = 16; off; off >>= 1)
            ssum += __shfl_xor_sync(0xffffffffu, ssum, off);
        float inv = 1.f / ssum;
        if (tx < 50) sProb[tx] = e0 * inv;
        if (tx < 18) sProb[tx + 32] = e1 * inv;
    }
    __syncthreads();

    // ---- phase 2: one float4 d-slot per thread (512*4 = 2048) ----
    const int d4 = tid * 4;
    #pragma unroll
    for (int bb = 0; bb < 2; ++bb) {
        const float* sProb = sm + F_PROB + 64 * bb;
        const float beta = sProb[KQ];
        const float* Vx = V + (size_t)(2 * b + bb) * KQ * DQ;
        const size_t base = (size_t)(2 * b + bb) * DQ;

        float4 cacc = make_float4(0.f, 0.f, 0.f, 0.f);
        #pragma unroll 7
        for (int l = 0; l < KQ; ++l) {
            const float p = sProb[l];
            const float4 v = __ldg((const float4*)(Vx + (size_t)l * DQ + d4));
            cacc.x = fmaf(p, v.x, cacc.x);
            cacc.y = fmaf(p, v.y, cacc.y);
            cacc.z = fmaf(p, v.z, cacc.z);
            cacc.w = fmaf(p, v.w, cacc.w);
        }
        const float4 sv = *(const float4*)(s_t + base + d4);
        const float4 hv = *(const float4*)(h_t + base + d4);
        const float om = 1.f - beta;
        float4 o;
        o.x = fmaf(beta, sv.x, fmaf(om, cacc.x, hv.x));
        o.y = fmaf(beta, sv.y, fmaf(om, cacc.y, hv.y));
        o.z = fmaf(beta, sv.z, fmaf(om, cacc.z, hv.z));
        o.w = fmaf(beta, sv.w, fmaf(om, cacc.w, hv.w));
        *(float4*)(out + base + d4) = o;
    }
}

// ---------------------------------------------------------------------------
extern "C" void kernel_launch(void* const* d_in, const int* in_sizes, int n_in,
                              void* d_out, int out_size) {
    (void)in_sizes; (void)n_in; (void)out_size;
    const float* V     = (const float*)d_in[0];
    const float* h_t   = (const float*)d_in[1];
    const float* s_t   = (const float*)d_in[2];
    const float* W_v   = (const float*)d_in[3];
    const float* W_g   = (const float*)d_in[4];
    const float* W_s   = (const float*)d_in[5];
    const float* w_h   = (const float*)d_in[6];
    const float* w_h_s = (const float*)d_in[7];
    float* out = (float*)d_out;

    k_wgt_sent<<<BQ / A_BM, 512>>>(h_t, s_t, W_g, W_s, w_h_s);

    cudaFuncSetAttribute(k_main, cudaFuncAttributeMaxDynamicSharedMemorySize,
                         SMEM_BYTES);
    k_main<<<BQ / BPC, 512, SMEM_BYTES>>>(V, h_t, s_t, W_v, w_h, out);
}